// round 1
// baseline (speedup 1.0000x reference)
#include <cuda_runtime.h>
#include <cuda_bf16.h>

// Problem dims (fixed)
#define BATCH 4
#define SEQ   4096
#define DIM   1024
#define MTOT  (BATCH * SEQ)   // 16384

// GEMM tiling
#define BM 128
#define BN 128
#define BK 8
#define TM 8
#define TN 8
#define NTHREADS 256

// Scratch (allocation-free rule: __device__ globals)
__device__ float g_Q[(size_t)MTOT * DIM];
__device__ float g_K[(size_t)MTOT * DIM];
__device__ float g_V[(size_t)MTOT * DIM];
__device__ float g_S[(size_t)BATCH * SEQ * SEQ];

// ---------------------------------------------------------------------------
// NT GEMM: C[M,N] = alpha * A[M,K] * B[N,K]^T   (row-major, dims % 128 == 0)
// causal!=0: skip tiles with n0 >= m0 + BM entirely (softmax never reads them)
// ---------------------------------------------------------------------------
__global__ void __launch_bounds__(NTHREADS)
gemm_nt(const float* __restrict__ A, const float* __restrict__ B,
        float* __restrict__ C, int M, int N, int K,
        long sA, long sB, long sC, float alpha, int causal)
{
    const int m0 = blockIdx.y * BM;
    const int n0 = blockIdx.x * BN;
    if (causal && n0 >= m0 + BM) return;

    A += (long)blockIdx.z * sA;
    B += (long)blockIdx.z * sB;
    C += (long)blockIdx.z * sC;

    __shared__ float As[BK][BM];
    __shared__ float Bs[BK][BN];

    const int tid = threadIdx.x;
    const int lr  = tid >> 1;           // 0..127 (tile row for global loads)
    const int lc  = (tid & 1) * 4;      // 0 or 4 (k offset, float4)
    const int tr  = (tid >> 4) * TM;    // micro-tile row base
    const int tc  = (tid & 15) * TN;    // micro-tile col base

    const float* Ap = A + (long)(m0 + lr) * K + lc;
    const float* Bp = B + (long)(n0 + lr) * K + lc;

    float acc[TM][TN];
    #pragma unroll
    for (int i = 0; i < TM; i++)
        #pragma unroll
        for (int j = 0; j < TN; j++) acc[i][j] = 0.f;

    for (int k0 = 0; k0 < K; k0 += BK) {
        float4 av = *(const float4*)(Ap + k0);
        float4 bv = *(const float4*)(Bp + k0);
        As[lc + 0][lr] = av.x; As[lc + 1][lr] = av.y;
        As[lc + 2][lr] = av.z; As[lc + 3][lr] = av.w;
        Bs[lc + 0][lr] = bv.x; Bs[lc + 1][lr] = bv.y;
        Bs[lc + 2][lr] = bv.z; Bs[lc + 3][lr] = bv.w;
        __syncthreads();
        #pragma unroll
        for (int kk = 0; kk < BK; kk++) {
            float a[TM], b[TN];
            #pragma unroll
            for (int i = 0; i < TM; i++) a[i] = As[kk][tr + i];
            #pragma unroll
            for (int j = 0; j < TN; j++) b[j] = Bs[kk][tc + j];
            #pragma unroll
            for (int i = 0; i < TM; i++)
                #pragma unroll
                for (int j = 0; j < TN; j++)
                    acc[i][j] = fmaf(a[i], b[j], acc[i][j]);
        }
        __syncthreads();
    }

    #pragma unroll
    for (int i = 0; i < TM; i++) {
        float* Cp = C + (long)(m0 + tr + i) * N + n0 + tc;
        #pragma unroll
        for (int j = 0; j < TN; j += 4) {
            float4 v = make_float4(alpha * acc[i][j],     alpha * acc[i][j + 1],
                                   alpha * acc[i][j + 2], alpha * acc[i][j + 3]);
            *(float4*)(Cp + j) = v;
        }
    }
}

// ---------------------------------------------------------------------------
// NN GEMM with causal K bound: C[M,N] = A[M,K] * B[K,N], K-loop ends at m0+BM
// (A = softmax weights: rows are zero-padded up to their 128-tile boundary)
// ---------------------------------------------------------------------------
__global__ void __launch_bounds__(NTHREADS)
gemm_nn_causal(const float* __restrict__ A, const float* __restrict__ B,
               float* __restrict__ C, int M, int N, int K,
               long sA, long sB, long sC)
{
    const int m0 = blockIdx.y * BM;
    const int n0 = blockIdx.x * BN;
    A += (long)blockIdx.z * sA;
    B += (long)blockIdx.z * sB;
    C += (long)blockIdx.z * sC;

    __shared__ float As[BK][BM];
    __shared__ float Bs[BK][BN];

    const int tid = threadIdx.x;
    const int lr  = tid >> 1;
    const int lc  = (tid & 1) * 4;
    const int kr  = tid >> 5;          // 0..7   (B tile row)
    const int kc  = (tid & 31) * 4;    // 0..124 (B tile col, float4)
    const int tr  = (tid >> 4) * TM;
    const int tc  = (tid & 15) * TN;

    const float* Ap = A + (long)(m0 + lr) * K + lc;
    const float* Bp = B + (long)kr * N + n0 + kc;

    const int kend = min(K, m0 + BM);   // causal bound (multiple of BK)

    float acc[TM][TN];
    #pragma unroll
    for (int i = 0; i < TM; i++)
        #pragma unroll
        for (int j = 0; j < TN; j++) acc[i][j] = 0.f;

    for (int k0 = 0; k0 < kend; k0 += BK) {
        float4 av = *(const float4*)(Ap + k0);
        float4 bv = *(const float4*)(Bp + (long)k0 * N);
        As[lc + 0][lr] = av.x; As[lc + 1][lr] = av.y;
        As[lc + 2][lr] = av.z; As[lc + 3][lr] = av.w;
        *(float4*)&Bs[kr][kc] = bv;
        __syncthreads();
        #pragma unroll
        for (int kk = 0; kk < BK; kk++) {
            float a[TM], b[TN];
            #pragma unroll
            for (int i = 0; i < TM; i++) a[i] = As[kk][tr + i];
            #pragma unroll
            for (int j = 0; j < TN; j++) b[j] = Bs[kk][tc + j];
            #pragma unroll
            for (int i = 0; i < TM; i++)
                #pragma unroll
                for (int j = 0; j < TN; j++)
                    acc[i][j] = fmaf(a[i], b[j], acc[i][j]);
        }
        __syncthreads();
    }

    #pragma unroll
    for (int i = 0; i < TM; i++) {
        float* Cp = C + (long)(m0 + tr + i) * N + n0 + tc;
        #pragma unroll
        for (int j = 0; j < TN; j += 4)
            *(float4*)(Cp + j) = make_float4(acc[i][j], acc[i][j + 1],
                                             acc[i][j + 2], acc[i][j + 3]);
    }
}

// ---------------------------------------------------------------------------
// Causal row softmax, in place. One block per (b,q) row.
// Valid entries: k in [0, q]. Zero-fills (q, zend) where zend = row-tile end,
// so the PV GEMM's K-loop (bounded at the tile diagonal) reads only zeros there.
// ---------------------------------------------------------------------------
__global__ void __launch_bounds__(256)
softmax_causal(float* __restrict__ S_, int S)
{
    const long row = blockIdx.x;            // b*S + q
    const int  q   = (int)(row & (long)(S - 1));
    float* p = S_ + row * (long)S;
    const int n = q + 1;

    __shared__ float buf[SEQ];
    __shared__ float red[256];
    const int tid = threadIdx.x;

    float lmax = -3.4e38f;
    for (int i = tid; i < n; i += 256) {
        float v = p[i];
        buf[i] = v;
        lmax = fmaxf(lmax, v);
    }
    red[tid] = lmax;
    __syncthreads();
    #pragma unroll
    for (int s = 128; s > 0; s >>= 1) {
        if (tid < s) red[tid] = fmaxf(red[tid], red[tid + s]);
        __syncthreads();
    }
    const float m = red[0];
    __syncthreads();

    float lsum = 0.f;
    for (int i = tid; i < n; i += 256) {
        float e = __expf(buf[i] - m);
        buf[i] = e;
        lsum += e;
    }
    red[tid] = lsum;
    __syncthreads();
    #pragma unroll
    for (int s = 128; s > 0; s >>= 1) {
        if (tid < s) red[tid] += red[tid + s];
        __syncthreads();
    }
    const float inv = 1.0f / red[0];
    __syncthreads();

    for (int i = tid; i < n; i += 256) p[i] = buf[i] * inv;
    const int zend = ((q >> 7) + 1) << 7;   // next multiple of BM=128
    for (int i = n + tid; i < zend; i += 256) p[i] = 0.f;
}

// ---------------------------------------------------------------------------
extern "C" void kernel_launch(void* const* d_in, const int* in_sizes, int n_in,
                              void* d_out, int out_size)
{
    const float* x  = (const float*)d_in[0];
    const float* Wq = (const float*)d_in[1];
    const float* Wk = (const float*)d_in[2];
    const float* Wv = (const float*)d_in[3];
    float* out = (float*)d_out;

    float *Q, *K, *V, *Sc;
    cudaGetSymbolAddress((void**)&Q,  g_Q);
    cudaGetSymbolAddress((void**)&K,  g_K);
    cudaGetSymbolAddress((void**)&V,  g_V);
    cudaGetSymbolAddress((void**)&Sc, g_S);

    // QKV projections: [16384,1024] = x[16384,1024] * W[1024,1024]^T
    dim3 gProj(DIM / BN, MTOT / BM, 1);
    gemm_nt<<<gProj, NTHREADS>>>(x, Wq, Q, MTOT, DIM, DIM, 0, 0, 0, 1.0f, 0);
    gemm_nt<<<gProj, NTHREADS>>>(x, Wk, K, MTOT, DIM, DIM, 0, 0, 0, 1.0f, 0);
    gemm_nt<<<gProj, NTHREADS>>>(x, Wv, V, MTOT, DIM, DIM, 0, 0, 0, 1.0f, 0);

    // scores = (1/sqrt(DK)) * Q K^T per batch, causal tile skip
    const long sQK = (long)SEQ * DIM;
    const long sSS = (long)SEQ * SEQ;
    dim3 gScore(SEQ / BN, SEQ / BM, BATCH);
    gemm_nt<<<gScore, NTHREADS>>>(Q, K, Sc, SEQ, SEQ, DIM,
                                  sQK, sQK, sSS, 0.03125f /*1/32*/, 1);

    // causal softmax in place
    softmax_causal<<<BATCH * SEQ, 256>>>(Sc, SEQ);

    // out = P V per batch (K-loop causally bounded)
    dim3 gPV(DIM / BN, SEQ / BM, BATCH);
    gemm_nn_causal<<<gPV, NTHREADS>>>(Sc, V, out, SEQ, DIM, SEQ,
                                      sSS, sQK, sQK);
}

// round 4
// speedup vs baseline: 2.5259x; 2.5259x over previous
#include <cuda_runtime.h>
#include <cstdint>

#define BATCH 4
#define SEQ   4096
#define DIM   1024
#define MTOT  (BATCH * SEQ)      // 16384

#define BM 128
#define BN 128
#define BK 32
#define NTHR 256
#define PADS 36                   // smem row stride in floats (bank-conflict-free)
#define BUF_FLOATS (BM * PADS)    // 4608 floats = 18432 B per tile buffer
#define SMEM_DYN (4 * BUF_FLOATS * 4)   // A0,B0,A1,B1 = 73728 B

// Scratch (allocation-free rule: __device__ globals)
__device__ float g_Q[(size_t)MTOT * DIM];
__device__ float g_K[(size_t)MTOT * DIM];
__device__ float g_V[(size_t)MTOT * DIM];          // holds V^T: [DIM][MTOT]
__device__ float g_S[(size_t)BATCH * SEQ * SEQ];

// ---------------------------------------------------------------------------
static __device__ __forceinline__ uint32_t s2u(const void* p) {
    uint32_t a;
    asm("{ .reg .u64 t; cvta.to.shared.u64 t, %1; cvt.u32.u64 %0, t; }"
        : "=r"(a) : "l"(p));
    return a;
}
static __device__ __forceinline__ uint32_t f2tf32(float f) {
    uint32_t r;
    asm("cvt.rna.tf32.f32 %0, %1;" : "=r"(r) : "f"(f));
    return r;
}
static __device__ __forceinline__ void sts4_tf32(float* dst, float4 v) {
    asm volatile("st.shared.v4.b32 [%0], {%1,%2,%3,%4};"
                 :: "r"(s2u(dst)), "r"(f2tf32(v.x)), "r"(f2tf32(v.y)),
                    "r"(f2tf32(v.z)), "r"(f2tf32(v.w)) : "memory");
}
static __device__ __forceinline__ void mma_tf32(float* c, uint32_t a0, uint32_t a1,
                                                uint32_t a2, uint32_t a3,
                                                uint32_t b0, uint32_t b1) {
    asm volatile(
        "mma.sync.aligned.m16n8k8.row.col.f32.tf32.tf32.f32 "
        "{%0,%1,%2,%3}, {%4,%5,%6,%7}, {%8,%9}, {%0,%1,%2,%3};"
        : "+f"(c[0]), "+f"(c[1]), "+f"(c[2]), "+f"(c[3])
        : "r"(a0), "r"(a1), "r"(a2), "r"(a3), "r"(b0), "r"(b1));
}

// ---------------------------------------------------------------------------
// tf32 mma.sync NT GEMM: C[m][n] = alpha * sum_k A[m][k] * B[n][k]
// flags: 1 = causal tile skip (n0 > m0), 2 = transposed epilogue (C[n][m]),
//        4 = causal K bound (kend = m0 + BM)
// ---------------------------------------------------------------------------
__global__ void __launch_bounds__(NTHR)
gemm_mma(const float* __restrict__ A, const float* __restrict__ B,
         float* __restrict__ C, int K, int lda, int ldb, int ldc,
         long sA, long sB, long sC, float alpha, int flags)
{
    const int m0 = blockIdx.y * BM;
    const int n0 = blockIdx.x * BN;
    if ((flags & 1) && n0 > m0) return;

    A += (long)blockIdx.z * sA;
    B += (long)blockIdx.z * sB;
    C += (long)blockIdx.z * sC;

    extern __shared__ float sm[];
    float* const Abuf[2] = { sm,                  sm + 2 * BUF_FLOATS };
    float* const Bbuf[2] = { sm + BUF_FLOATS,     sm + 3 * BUF_FLOATS };

    const int tid  = threadIdx.x;
    const int lane = tid & 31;
    const int w    = tid >> 5;
    const int wm   = (w >> 2) * 64;     // warp tile M origin (0 or 64)
    const int wn   = (w & 3) * 32;      // warp tile N origin (0..96)
    const int g    = lane >> 2;         // 0..7
    const int t4   = lane & 3;          // 0..3

    const int kend = (flags & 4) ? min(K, m0 + BM) : K;
    const int nc   = kend / BK;

    // Global load geometry: 4 float4 per thread per operand per chunk
    const int lr  = tid >> 3;           // 0..31 base row
    const int lc4 = (tid & 7) * 4;      // float col 0,4,...,28
    const float* Ap[4]; const float* Bp[4];
    int so[4];
    #pragma unroll
    for (int i = 0; i < 4; i++) {
        const int row = lr + 32 * i;
        Ap[i] = A + (long)(m0 + row) * lda + lc4;
        Bp[i] = B + (long)(n0 + row) * ldb + lc4;
        so[i] = row * PADS + lc4;
    }

    float acc[4][4][4];
    #pragma unroll
    for (int i = 0; i < 4; i++)
        #pragma unroll
        for (int j = 0; j < 4; j++)
            #pragma unroll
            for (int k = 0; k < 4; k++) acc[i][j][k] = 0.f;

    // prologue: chunk 0 -> buffer 0
    {
        #pragma unroll
        for (int i = 0; i < 4; i++) {
            sts4_tf32(Abuf[0] + so[i], *(const float4*)Ap[i]);
            sts4_tf32(Bbuf[0] + so[i], *(const float4*)Bp[i]);
        }
    }
    __syncthreads();

    for (int c = 0; c < nc; c++) {
        float4 ra[4], rb[4];
        const bool more = (c + 1 < nc);
        if (more) {
            const long k0 = (long)(c + 1) * BK;
            #pragma unroll
            for (int i = 0; i < 4; i++) {
                ra[i] = *(const float4*)(Ap[i] + k0);
                rb[i] = *(const float4*)(Bp[i] + k0);
            }
        }

        const uint32_t* Au = (const uint32_t*)Abuf[c & 1];
        const uint32_t* Bu = (const uint32_t*)Bbuf[c & 1];
        #pragma unroll
        for (int ks = 0; ks < 4; ks++) {
            const int k0 = ks * 8;
            uint32_t af[4][4];
            #pragma unroll
            for (int tm = 0; tm < 4; tm++) {
                const int m = wm + tm * 16 + g;
                af[tm][0] = Au[m * PADS + k0 + t4];
                af[tm][1] = Au[(m + 8) * PADS + k0 + t4];
                af[tm][2] = Au[m * PADS + k0 + t4 + 4];
                af[tm][3] = Au[(m + 8) * PADS + k0 + t4 + 4];
            }
            uint32_t bf[4][2];
            #pragma unroll
            for (int tn = 0; tn < 4; tn++) {
                const int n = wn + tn * 8 + g;
                bf[tn][0] = Bu[n * PADS + k0 + t4];
                bf[tn][1] = Bu[n * PADS + k0 + t4 + 4];
            }
            #pragma unroll
            for (int tm = 0; tm < 4; tm++)
                #pragma unroll
                for (int tn = 0; tn < 4; tn++)
                    mma_tf32(acc[tm][tn], af[tm][0], af[tm][1], af[tm][2],
                             af[tm][3], bf[tn][0], bf[tn][1]);
        }

        if (more) {
            #pragma unroll
            for (int i = 0; i < 4; i++) {
                sts4_tf32(Abuf[(c + 1) & 1] + so[i], ra[i]);
                sts4_tf32(Bbuf[(c + 1) & 1] + so[i], rb[i]);
            }
        }
        __syncthreads();
    }

    // Epilogue. Thread owns (row = wm+tm*16+g[+8], cols = wn+tn*8+t4*2, +1)
    if (flags & 2) {
        #pragma unroll
        for (int tm = 0; tm < 4; tm++) {
            const int mA = m0 + wm + tm * 16 + g;
            #pragma unroll
            for (int tn = 0; tn < 4; tn++) {
                const int n = n0 + wn + tn * 8 + t4 * 2;
                C[(long)n * ldc + mA]           = alpha * acc[tm][tn][0];
                C[(long)(n + 1) * ldc + mA]     = alpha * acc[tm][tn][1];
                C[(long)n * ldc + mA + 8]       = alpha * acc[tm][tn][2];
                C[(long)(n + 1) * ldc + mA + 8] = alpha * acc[tm][tn][3];
            }
        }
    } else {
        #pragma unroll
        for (int tm = 0; tm < 4; tm++) {
            const int mA = m0 + wm + tm * 16 + g;
            #pragma unroll
            for (int tn = 0; tn < 4; tn++) {
                const int n = n0 + wn + tn * 8 + t4 * 2;
                *(float2*)(C + (long)mA * ldc + n) =
                    make_float2(alpha * acc[tm][tn][0], alpha * acc[tm][tn][1]);
                *(float2*)(C + (long)(mA + 8) * ldc + n) =
                    make_float2(alpha * acc[tm][tn][2], alpha * acc[tm][tn][3]);
            }
        }
    }
}

// ---------------------------------------------------------------------------
// Causal row softmax, in place. Zero-fills (q, 128-tile boundary) so PV's
// causal K bound reads only zeros past the diagonal.
// ---------------------------------------------------------------------------
__global__ void __launch_bounds__(256)
softmax_causal(float* __restrict__ S_, int S)
{
    const long row = blockIdx.x;            // b*S + q
    const int  q   = (int)(row & (long)(S - 1));
    float* p = S_ + row * (long)S;
    const int n = q + 1;

    __shared__ float buf[SEQ];
    __shared__ float red[256];
    const int tid = threadIdx.x;

    float lmax = -3.4e38f;
    for (int i = tid; i < n; i += 256) {
        float v = p[i];
        buf[i] = v;
        lmax = fmaxf(lmax, v);
    }
    red[tid] = lmax;
    __syncthreads();
    #pragma unroll
    for (int s = 128; s > 0; s >>= 1) {
        if (tid < s) red[tid] = fmaxf(red[tid], red[tid + s]);
        __syncthreads();
    }
    const float m = red[0];
    __syncthreads();

    float lsum = 0.f;
    for (int i = tid; i < n; i += 256) {
        float e = __expf(buf[i] - m);
        buf[i] = e;
        lsum += e;
    }
    red[tid] = lsum;
    __syncthreads();
    #pragma unroll
    for (int s = 128; s > 0; s >>= 1) {
        if (tid < s) red[tid] += red[tid + s];
        __syncthreads();
    }
    const float inv = 1.0f / red[0];
    __syncthreads();

    for (int i = tid; i < n; i += 256) p[i] = buf[i] * inv;
    const int zend = ((q >> 7) + 1) << 7;   // next multiple of BM=128
    for (int i = n + tid; i < zend; i += 256) p[i] = 0.f;
}

// ---------------------------------------------------------------------------
extern "C" void kernel_launch(void* const* d_in, const int* in_sizes, int n_in,
                              void* d_out, int out_size)
{
    const float* x  = (const float*)d_in[0];
    const float* Wq = (const float*)d_in[1];
    const float* Wk = (const float*)d_in[2];
    const float* Wv = (const float*)d_in[3];
    float* out = (float*)d_out;

    float *Q, *Kd, *Vt, *Sc;
    cudaGetSymbolAddress((void**)&Q,  g_Q);
    cudaGetSymbolAddress((void**)&Kd, g_K);
    cudaGetSymbolAddress((void**)&Vt, g_V);
    cudaGetSymbolAddress((void**)&Sc, g_S);

    cudaFuncSetAttribute(gemm_mma, cudaFuncAttributeMaxDynamicSharedMemorySize,
                         SMEM_DYN);

    // QKV projections: [16384,1024] = x * W^T ; V written transposed (Vt)
    dim3 gP(DIM / BN, MTOT / BM, 1);
    gemm_mma<<<gP, NTHR, SMEM_DYN>>>(x, Wq, Q,  DIM, DIM, DIM, DIM,
                                     0, 0, 0, 1.0f, 0);
    gemm_mma<<<gP, NTHR, SMEM_DYN>>>(x, Wk, Kd, DIM, DIM, DIM, DIM,
                                     0, 0, 0, 1.0f, 0);
    gemm_mma<<<gP, NTHR, SMEM_DYN>>>(x, Wv, Vt, DIM, DIM, DIM, MTOT,
                                     0, 0, 0, 1.0f, 2);   // transC

    // scores = (1/32) * Q K^T per batch, causal tile skip
    const long sQK = (long)SEQ * DIM;
    const long sSS = (long)SEQ * SEQ;
    dim3 gS(SEQ / BN, SEQ / BM, BATCH);
    gemm_mma<<<gS, NTHR, SMEM_DYN>>>(Q, Kd, Sc, DIM, DIM, DIM, SEQ,
                                     sQK, sQK, sSS, 0.03125f, 1);

    softmax_causal<<<BATCH * SEQ, 256>>>(Sc, SEQ);

    // out = P V per batch : NT with B = Vt (ldb = MTOT), causal K bound
    dim3 gPV(DIM / BN, SEQ / BM, BATCH);
    gemm_mma<<<gPV, NTHR, SMEM_DYN>>>(Sc, Vt, out, SEQ, SEQ, MTOT, DIM,
                                      sSS, (long)SEQ, sQK, 1.0f, 4);
}

// round 7
// speedup vs baseline: 4.0293x; 1.5952x over previous
#include <cuda_runtime.h>
#include <cstdint>

#define BATCH 4
#define SEQ   4096
#define DIM   1024
#define MTOT  (BATCH * SEQ)      // 16384

#define BM 128
#define BN 128
#define BK 32
#define NTHR 256
#define PADS 36                   // smem row stride in floats (bank-conflict-free)
#define BUF_FLOATS (BM * PADS)    // 4608 floats = 18432 B per tile buffer
#define BUF_BYTES  (BUF_FLOATS * 4)
#define SMEM_DYN (4 * BUF_BYTES)  // A0,B0,A1,B1 = 73728 B

// Scratch (allocation-free rule: __device__ globals)
__device__ float g_Q[(size_t)MTOT * DIM];
__device__ float g_K[(size_t)MTOT * DIM];
__device__ float g_V[(size_t)MTOT * DIM];          // holds V^T: [DIM][MTOT]
__device__ float g_S[(size_t)BATCH * SEQ * SEQ];
__device__ float g_X[(size_t)MTOT * DIM];          // tf32-rounded x
__device__ float g_Wq[(size_t)DIM * DIM];
__device__ float g_Wk[(size_t)DIM * DIM];
__device__ float g_Wv[(size_t)DIM * DIM];

// ---------------------------------------------------------------------------
static __device__ __forceinline__ uint32_t s2u(const void* p) {
    uint32_t a;
    asm("{ .reg .u64 t; cvta.to.shared.u64 t, %1; cvt.u32.u64 %0, t; }"
        : "=r"(a) : "l"(p));
    return a;
}
static __device__ __forceinline__ uint32_t f2tf32(float f) {
    uint32_t r;
    asm("cvt.rna.tf32.f32 %0, %1;" : "=r"(r) : "f"(f));
    return r;
}
static __device__ __forceinline__ float rtf(float f) {
    return __uint_as_float(f2tf32(f));
}
static __device__ __forceinline__ void cpasync16(uint32_t saddr, const void* gaddr) {
    asm volatile("cp.async.cg.shared.global [%0], [%1], 16;"
                 :: "r"(saddr), "l"(gaddr) : "memory");
}
static __device__ __forceinline__ void cpcommit() {
    asm volatile("cp.async.commit_group;" ::: "memory");
}
static __device__ __forceinline__ void cpwait0() {
    asm volatile("cp.async.wait_group 0;" ::: "memory");
}
static __device__ __forceinline__ void cpwait1() {
    asm volatile("cp.async.wait_group 1;" ::: "memory");
}
static __device__ __forceinline__ void mma_tf32(float* c, uint32_t a0, uint32_t a1,
                                                uint32_t a2, uint32_t a3,
                                                uint32_t b0, uint32_t b1) {
    asm volatile(
        "mma.sync.aligned.m16n8k8.row.col.f32.tf32.tf32.f32 "
        "{%0,%1,%2,%3}, {%4,%5,%6,%7}, {%8,%9}, {%0,%1,%2,%3};"
        : "+f"(c[0]), "+f"(c[1]), "+f"(c[2]), "+f"(c[3])
        : "r"(a0), "r"(a1), "r"(a2), "r"(a3), "r"(b0), "r"(b1));
}

// ---------------------------------------------------------------------------
// Pre-round a tensor to tf32 (rna) in place-or-copy, float4 granularity.
// ---------------------------------------------------------------------------
__global__ void __launch_bounds__(256)
round_tf32(const float4* __restrict__ in, float4* __restrict__ out, int n4)
{
    int i = blockIdx.x * 256 + threadIdx.x;
    if (i < n4) {
        float4 v = in[i];
        out[i] = make_float4(rtf(v.x), rtf(v.y), rtf(v.z), rtf(v.w));
    }
}

// ---------------------------------------------------------------------------
// tf32 mma.sync NT GEMM: C[m][n] = alpha * sum_k A[m][k] * B[n][k]
// Inputs must already be tf32-rounded. cp.async double-buffered mainloop.
// flags: 1 = causal tile skip (n0 > m0), 2 = transposed epilogue (C[n][m]),
//        4 = causal K bound (kend = m0 + BM), 8 = round output to tf32
// ---------------------------------------------------------------------------
__global__ void __launch_bounds__(NTHR, 2)
gemm_mma(const float* __restrict__ A, const float* __restrict__ B,
         float* __restrict__ C, int K, int lda, int ldb, int ldc,
         long sA, long sB, long sC, float alpha, int flags)
{
    const int m0 = blockIdx.y * BM;
    const int n0 = blockIdx.x * BN;
    if ((flags & 1) && n0 > m0) return;

    A += (long)blockIdx.z * sA;
    B += (long)blockIdx.z * sB;
    C += (long)blockIdx.z * sC;

    extern __shared__ float smf[];
    const uint32_t sa = s2u(smf);

    const int tid  = threadIdx.x;
    const int lane = tid & 31;
    const int w    = tid >> 5;
    const int wm   = (w >> 2) * 64;     // warp tile M origin (0 or 64)
    const int wn   = (w & 3) * 32;      // warp tile N origin (0..96)
    const int g    = lane >> 2;         // 0..7
    const int t4   = lane & 3;          // 0..3

    const int kend = (flags & 4) ? min(K, m0 + BM) : K;
    const int nc   = kend / BK;

    // Global->smem geometry: 4 x 16B cp.async per thread per operand per chunk
    const int lr  = tid >> 3;           // 0..31 base row
    const int lc4 = (tid & 7) * 4;      // float col 0,4,...,28
    const float* Ag[4]; const float* Bg[4];
    uint32_t sob[4];                    // smem byte offset within a buffer
    #pragma unroll
    for (int i = 0; i < 4; i++) {
        const int row = lr + 32 * i;
        Ag[i] = A + (long)(m0 + row) * lda + lc4;
        Bg[i] = B + (long)(n0 + row) * ldb + lc4;
        sob[i] = (uint32_t)(row * PADS + lc4) * 4u;
    }

    float acc[4][4][4];
    #pragma unroll
    for (int i = 0; i < 4; i++)
        #pragma unroll
        for (int j = 0; j < 4; j++)
            #pragma unroll
            for (int k = 0; k < 4; k++) acc[i][j][k] = 0.f;

    // prologue: issue chunk 0 into stage 0
    {
        const uint32_t ab = sa;                 // A stage0
        const uint32_t bb = sa + BUF_BYTES;     // B stage0
        #pragma unroll
        for (int i = 0; i < 4; i++) {
            cpasync16(ab + sob[i], Ag[i]);
            cpasync16(bb + sob[i], Bg[i]);
            Ag[i] += BK; Bg[i] += BK;
        }
        cpcommit();
    }

    for (int c = 0; c < nc; c++) {
        const bool more = (c + 1 < nc);
        if (more) {
            const uint32_t st = (uint32_t)((c + 1) & 1) * 2u * BUF_BYTES;
            const uint32_t ab = sa + st;
            const uint32_t bb = sa + st + BUF_BYTES;
            #pragma unroll
            for (int i = 0; i < 4; i++) {
                cpasync16(ab + sob[i], Ag[i]);
                cpasync16(bb + sob[i], Bg[i]);
                Ag[i] += BK; Bg[i] += BK;
            }
            cpcommit();
            cpwait1();          // chunk c's group complete
        } else {
            cpwait0();
        }
        __syncthreads();

        const uint32_t* Au = (const uint32_t*)(smf + (c & 1) * 2 * BUF_FLOATS);
        const uint32_t* Bu = Au + BUF_FLOATS;
        #pragma unroll
        for (int ks = 0; ks < 4; ks++) {
            const int k0 = ks * 8;
            uint32_t af[4][4];
            #pragma unroll
            for (int tm = 0; tm < 4; tm++) {
                const int m = wm + tm * 16 + g;
                af[tm][0] = Au[m * PADS + k0 + t4];
                af[tm][1] = Au[(m + 8) * PADS + k0 + t4];
                af[tm][2] = Au[m * PADS + k0 + t4 + 4];
                af[tm][3] = Au[(m + 8) * PADS + k0 + t4 + 4];
            }
            uint32_t bf[4][2];
            #pragma unroll
            for (int tn = 0; tn < 4; tn++) {
                const int n = wn + tn * 8 + g;
                bf[tn][0] = Bu[n * PADS + k0 + t4];
                bf[tn][1] = Bu[n * PADS + k0 + t4 + 4];
            }
            #pragma unroll
            for (int tm = 0; tm < 4; tm++)
                #pragma unroll
                for (int tn = 0; tn < 4; tn++)
                    mma_tf32(acc[tm][tn], af[tm][0], af[tm][1], af[tm][2],
                             af[tm][3], bf[tn][0], bf[tn][1]);
        }
        __syncthreads();   // all warps done reading stage c before it is refilled
    }

    // Epilogue. Thread owns (row = wm+tm*16+g[+8], cols = wn+tn*8+t4*2, +1)
    const bool rnd = (flags & 8) != 0;
    if (flags & 2) {
        #pragma unroll
        for (int tm = 0; tm < 4; tm++) {
            const int mA = m0 + wm + tm * 16 + g;
            #pragma unroll
            for (int tn = 0; tn < 4; tn++) {
                const int n = n0 + wn + tn * 8 + t4 * 2;
                float v0 = alpha * acc[tm][tn][0], v1 = alpha * acc[tm][tn][1];
                float v2 = alpha * acc[tm][tn][2], v3 = alpha * acc[tm][tn][3];
                if (rnd) { v0 = rtf(v0); v1 = rtf(v1); v2 = rtf(v2); v3 = rtf(v3); }
                C[(long)n * ldc + mA]           = v0;
                C[(long)(n + 1) * ldc + mA]     = v1;
                C[(long)n * ldc + mA + 8]       = v2;
                C[(long)(n + 1) * ldc + mA + 8] = v3;
            }
        }
    } else {
        #pragma unroll
        for (int tm = 0; tm < 4; tm++) {
            const int mA = m0 + wm + tm * 16 + g;
            #pragma unroll
            for (int tn = 0; tn < 4; tn++) {
                const int n = n0 + wn + tn * 8 + t4 * 2;
                float v0 = alpha * acc[tm][tn][0], v1 = alpha * acc[tm][tn][1];
                float v2 = alpha * acc[tm][tn][2], v3 = alpha * acc[tm][tn][3];
                if (rnd) { v0 = rtf(v0); v1 = rtf(v1); v2 = rtf(v2); v3 = rtf(v3); }
                *(float2*)(C + (long)mA * ldc + n)       = make_float2(v0, v1);
                *(float2*)(C + (long)(mA + 8) * ldc + n) = make_float2(v2, v3);
            }
        }
    }
}

// ---------------------------------------------------------------------------
// Causal row softmax, in place. Writes tf32-rounded P (PV GEMM input) and
// zero-fills (q, 128-tile boundary) so PV's causal K bound reads only zeros.
// ---------------------------------------------------------------------------
__global__ void __launch_bounds__(256)
softmax_causal(float* __restrict__ S_, int S)
{
    const long row = blockIdx.x;            // b*S + q
    const int  q   = (int)(row & (long)(S - 1));
    float* p = S_ + row * (long)S;
    const int n = q + 1;

    __shared__ float buf[SEQ];
    __shared__ float red[256];
    const int tid = threadIdx.x;

    float lmax = -3.4e38f;
    for (int i = tid; i < n; i += 256) {
        float v = p[i];
        buf[i] = v;
        lmax = fmaxf(lmax, v);
    }
    red[tid] = lmax;
    __syncthreads();
    #pragma unroll
    for (int s = 128; s > 0; s >>= 1) {
        if (tid < s) red[tid] = fmaxf(red[tid], red[tid + s]);
        __syncthreads();
    }
    const float m = red[0];
    __syncthreads();

    float lsum = 0.f;
    for (int i = tid; i < n; i += 256) {
        float e = __expf(buf[i] - m);
        buf[i] = e;
        lsum += e;
    }
    red[tid] = lsum;
    __syncthreads();
    #pragma unroll
    for (int s = 128; s > 0; s >>= 1) {
        if (tid < s) red[tid] += red[tid + s];
        __syncthreads();
    }
    const float inv = 1.0f / red[0];
    __syncthreads();

    for (int i = tid; i < n; i += 256) p[i] = rtf(buf[i] * inv);
    const int zend = ((q >> 7) + 1) << 7;   // next multiple of BM=128
    for (int i = n + tid; i < zend; i += 256) p[i] = 0.f;
}

// ---------------------------------------------------------------------------
extern "C" void kernel_launch(void* const* d_in, const int* in_sizes, int n_in,
                              void* d_out, int out_size)
{
    const float* x  = (const float*)d_in[0];
    const float* Wq = (const float*)d_in[1];
    const float* Wk = (const float*)d_in[2];
    const float* Wv = (const float*)d_in[3];
    float* out = (float*)d_out;

    float *Q, *Kd, *Vt, *Sc, *Xr, *Wqr, *Wkr, *Wvr;
    cudaGetSymbolAddress((void**)&Q,   g_Q);
    cudaGetSymbolAddress((void**)&Kd,  g_K);
    cudaGetSymbolAddress((void**)&Vt,  g_V);
    cudaGetSymbolAddress((void**)&Sc,  g_S);
    cudaGetSymbolAddress((void**)&Xr,  g_X);
    cudaGetSymbolAddress((void**)&Wqr, g_Wq);
    cudaGetSymbolAddress((void**)&Wkr, g_Wk);
    cudaGetSymbolAddress((void**)&Wvr, g_Wv);

    cudaFuncSetAttribute(gemm_mma, cudaFuncAttributeMaxDynamicSharedMemorySize,
                         SMEM_DYN);

    // tf32-round all GEMM inputs once
    const int nx4 = (MTOT * DIM) / 4, nw4 = (DIM * DIM) / 4;
    round_tf32<<<(nx4 + 255) / 256, 256>>>((const float4*)x,  (float4*)Xr,  nx4);
    round_tf32<<<(nw4 + 255) / 256, 256>>>((const float4*)Wq, (float4*)Wqr, nw4);
    round_tf32<<<(nw4 + 255) / 256, 256>>>((const float4*)Wk, (float4*)Wkr, nw4);
    round_tf32<<<(nw4 + 255) / 256, 256>>>((const float4*)Wv, (float4*)Wvr, nw4);

    // QKV projections (outputs tf32-rounded); V written transposed (Vt)
    dim3 gP(DIM / BN, MTOT / BM, 1);
    gemm_mma<<<gP, NTHR, SMEM_DYN>>>(Xr, Wqr, Q,  DIM, DIM, DIM, DIM,
                                     0, 0, 0, 1.0f, 8);
    gemm_mma<<<gP, NTHR, SMEM_DYN>>>(Xr, Wkr, Kd, DIM, DIM, DIM, DIM,
                                     0, 0, 0, 1.0f, 8);
    gemm_mma<<<gP, NTHR, SMEM_DYN>>>(Xr, Wvr, Vt, DIM, DIM, DIM, MTOT,
                                     0, 0, 0, 1.0f, 2 | 8);   // transC + round

    // scores = (1/32) * Q K^T per batch, causal tile skip (no rounding)
    const long sQK = (long)SEQ * DIM;
    const long sSS = (long)SEQ * SEQ;
    dim3 gS(SEQ / BN, SEQ / BM, BATCH);
    gemm_mma<<<gS, NTHR, SMEM_DYN>>>(Q, Kd, Sc, DIM, DIM, DIM, SEQ,
                                     sQK, sQK, sSS, 0.03125f, 1);

    softmax_causal<<<BATCH * SEQ, 256>>>(Sc, SEQ);

    // out = P V per batch : NT with B = Vt (ldb = MTOT), causal K bound
    dim3 gPV(DIM / BN, SEQ / BM, BATCH);
    gemm_mma<<<gPV, NTHR, SMEM_DYN>>>(Sc, Vt, out, SEQ, SEQ, MTOT, DIM,
                                      sSS, (long)SEQ, sQK, 1.0f, 4);
}

// round 8
// speedup vs baseline: 4.0947x; 1.0162x over previous
#include <cuda_runtime.h>
#include <cstdint>

#define BATCH 4
#define SEQ   4096
#define DIM   1024
#define MTOT  (BATCH * SEQ)      // 16384

#define BM 128
#define BN 128
#define BK 32
#define NTHR 256
#define PADS 36                   // smem row stride in floats (bank-conflict-free)
#define BUF_FLOATS (BM * PADS)    // 4608 floats = 18432 B per tile buffer
#define BUF_BYTES  (BUF_FLOATS * 4)
#define NSTAGE 3
#define SMEM_DYN (NSTAGE * 2 * BUF_BYTES)   // 110592 B (2 CTAs/SM fit 228KB)

// Scratch (allocation-free rule: __device__ globals)
__device__ float g_Q[(size_t)MTOT * DIM];
__device__ float g_K[(size_t)MTOT * DIM];
__device__ float g_V[(size_t)MTOT * DIM];          // holds V^T: [DIM][MTOT]
__device__ float g_S[(size_t)BATCH * SEQ * SEQ];
__device__ float g_X[(size_t)MTOT * DIM];          // tf32-rounded x
__device__ float g_Wq[(size_t)DIM * DIM];
__device__ float g_Wk[(size_t)DIM * DIM];
__device__ float g_Wv[(size_t)DIM * DIM];

// ---------------------------------------------------------------------------
static __device__ __forceinline__ uint32_t s2u(const void* p) {
    uint32_t a;
    asm("{ .reg .u64 t; cvta.to.shared.u64 t, %1; cvt.u32.u64 %0, t; }"
        : "=r"(a) : "l"(p));
    return a;
}
static __device__ __forceinline__ uint32_t f2tf32(float f) {
    uint32_t r;
    asm("cvt.rna.tf32.f32 %0, %1;" : "=r"(r) : "f"(f));
    return r;
}
static __device__ __forceinline__ float rtf(float f) {
    return __uint_as_float(f2tf32(f));
}
static __device__ __forceinline__ void cpasync16(uint32_t saddr, const void* gaddr) {
    asm volatile("cp.async.cg.shared.global [%0], [%1], 16;"
                 :: "r"(saddr), "l"(gaddr) : "memory");
}
static __device__ __forceinline__ void cpcommit() {
    asm volatile("cp.async.commit_group;" ::: "memory");
}
static __device__ __forceinline__ void cpwait0() {
    asm volatile("cp.async.wait_group 0;" ::: "memory");
}
static __device__ __forceinline__ void cpwait1() {
    asm volatile("cp.async.wait_group 1;" ::: "memory");
}
static __device__ __forceinline__ void mma_tf32(float* c, uint32_t a0, uint32_t a1,
                                                uint32_t a2, uint32_t a3,
                                                uint32_t b0, uint32_t b1) {
    asm volatile(
        "mma.sync.aligned.m16n8k8.row.col.f32.tf32.tf32.f32 "
        "{%0,%1,%2,%3}, {%4,%5,%6,%7}, {%8,%9}, {%0,%1,%2,%3};"
        : "+f"(c[0]), "+f"(c[1]), "+f"(c[2]), "+f"(c[3])
        : "r"(a0), "r"(a1), "r"(a2), "r"(a3), "r"(b0), "r"(b1));
}

// ---------------------------------------------------------------------------
// Pre-round a tensor to tf32 (rna), float4 granularity.
// ---------------------------------------------------------------------------
__global__ void __launch_bounds__(256)
round_tf32(const float4* __restrict__ in, float4* __restrict__ out, int n4)
{
    int i = blockIdx.x * 256 + threadIdx.x;
    if (i < n4) {
        float4 v = in[i];
        out[i] = make_float4(rtf(v.x), rtf(v.y), rtf(v.z), rtf(v.w));
    }
}

// ---------------------------------------------------------------------------
// tf32 mma.sync NT GEMM: C[m][n] = alpha * sum_k A[m][k] * B[n][k]
// Inputs must already be tf32-rounded. 3-stage cp.async pipeline,
// one __syncthreads per K-chunk.
// flags: 1 = causal tile skip (n0 > m0), 2 = transposed epilogue (C[n][m]),
//        4 = causal K bound (kend = m0 + BM), 8 = round output to tf32
// ---------------------------------------------------------------------------
__global__ void __launch_bounds__(NTHR, 2)
gemm_mma(const float* __restrict__ A, const float* __restrict__ B,
         float* __restrict__ C, int K, int lda, int ldb, int ldc,
         long sA, long sB, long sC, float alpha, int flags)
{
    const int m0 = blockIdx.y * BM;
    const int n0 = blockIdx.x * BN;
    if ((flags & 1) && n0 > m0) return;

    A += (long)blockIdx.z * sA;
    B += (long)blockIdx.z * sB;
    C += (long)blockIdx.z * sC;

    extern __shared__ float smf[];
    const uint32_t sa = s2u(smf);

    const int tid  = threadIdx.x;
    const int lane = tid & 31;
    const int w    = tid >> 5;
    const int wm   = (w >> 2) * 64;     // warp tile M origin (0 or 64)
    const int wn   = (w & 3) * 32;      // warp tile N origin (0..96)
    const int g    = lane >> 2;         // 0..7
    const int t4   = lane & 3;          // 0..3

    const int kend = (flags & 4) ? min(K, m0 + BM) : K;
    const int nc   = kend / BK;

    // Global->smem geometry: 4 x 16B cp.async per thread per operand per chunk
    const int lr  = tid >> 3;           // 0..31 base row
    const int lc4 = (tid & 7) * 4;      // float col 0,4,...,28
    const float* Ag[4]; const float* Bg[4];
    uint32_t sob[4];                    // smem byte offset within a buffer
    #pragma unroll
    for (int i = 0; i < 4; i++) {
        const int row = lr + 32 * i;
        Ag[i] = A + (long)(m0 + row) * lda + lc4;
        Bg[i] = B + (long)(n0 + row) * ldb + lc4;
        sob[i] = (uint32_t)(row * PADS + lc4) * 4u;
    }

    float acc[4][4][4];
    #pragma unroll
    for (int i = 0; i < 4; i++)
        #pragma unroll
        for (int j = 0; j < 4; j++)
            #pragma unroll
            for (int k = 0; k < 4; k++) acc[i][j][k] = 0.f;

    // prologue: issue chunks 0 and 1 into stages 0 and 1
    {
        #pragma unroll
        for (int i = 0; i < 4; i++) {
            cpasync16(sa + sob[i], Ag[i]);
            cpasync16(sa + BUF_BYTES + sob[i], Bg[i]);
            Ag[i] += BK; Bg[i] += BK;
        }
        cpcommit();
    }
    if (nc > 1) {
        const uint32_t st = 2u * BUF_BYTES;
        #pragma unroll
        for (int i = 0; i < 4; i++) {
            cpasync16(sa + st + sob[i], Ag[i]);
            cpasync16(sa + st + BUF_BYTES + sob[i], Bg[i]);
            Ag[i] += BK; Bg[i] += BK;
        }
        cpcommit();
    }

    int stage = 0;            // stage holding chunk c
    int wstage = 2;           // stage to write chunk c+2 into
    for (int c = 0; c < nc; c++) {
        if (c + 1 < nc) cpwait1(); else cpwait0();   // group c complete
        __syncthreads();      // data visible; stage 'wstage' fully consumed

        if (c + 2 < nc) {
            const uint32_t st = (uint32_t)wstage * 2u * BUF_BYTES;
            #pragma unroll
            for (int i = 0; i < 4; i++) {
                cpasync16(sa + st + sob[i], Ag[i]);
                cpasync16(sa + st + BUF_BYTES + sob[i], Bg[i]);
                Ag[i] += BK; Bg[i] += BK;
            }
            cpcommit();
        }

        const uint32_t* Au = (const uint32_t*)(smf + stage * 2 * BUF_FLOATS);
        const uint32_t* Bu = Au + BUF_FLOATS;
        #pragma unroll
        for (int ks = 0; ks < 4; ks++) {
            const int k0 = ks * 8;
            uint32_t af[4][4];
            #pragma unroll
            for (int tm = 0; tm < 4; tm++) {
                const int m = wm + tm * 16 + g;
                af[tm][0] = Au[m * PADS + k0 + t4];
                af[tm][1] = Au[(m + 8) * PADS + k0 + t4];
                af[tm][2] = Au[m * PADS + k0 + t4 + 4];
                af[tm][3] = Au[(m + 8) * PADS + k0 + t4 + 4];
            }
            uint32_t bf[4][2];
            #pragma unroll
            for (int tn = 0; tn < 4; tn++) {
                const int n = wn + tn * 8 + g;
                bf[tn][0] = Bu[n * PADS + k0 + t4];
                bf[tn][1] = Bu[n * PADS + k0 + t4 + 4];
            }
            #pragma unroll
            for (int tm = 0; tm < 4; tm++)
                #pragma unroll
                for (int tn = 0; tn < 4; tn++)
                    mma_tf32(acc[tm][tn], af[tm][0], af[tm][1], af[tm][2],
                             af[tm][3], bf[tn][0], bf[tn][1]);
        }

        stage  = (stage == NSTAGE - 1) ? 0 : stage + 1;
        wstage = (wstage == NSTAGE - 1) ? 0 : wstage + 1;
    }

    // Epilogue. Thread owns (row = wm+tm*16+g[+8], cols = wn+tn*8+t4*2, +1)
    const bool rnd = (flags & 8) != 0;
    if (flags & 2) {
        #pragma unroll
        for (int tm = 0; tm < 4; tm++) {
            const int mA = m0 + wm + tm * 16 + g;
            #pragma unroll
            for (int tn = 0; tn < 4; tn++) {
                const int n = n0 + wn + tn * 8 + t4 * 2;
                float v0 = alpha * acc[tm][tn][0], v1 = alpha * acc[tm][tn][1];
                float v2 = alpha * acc[tm][tn][2], v3 = alpha * acc[tm][tn][3];
                if (rnd) { v0 = rtf(v0); v1 = rtf(v1); v2 = rtf(v2); v3 = rtf(v3); }
                C[(long)n * ldc + mA]           = v0;
                C[(long)(n + 1) * ldc + mA]     = v1;
                C[(long)n * ldc + mA + 8]       = v2;
                C[(long)(n + 1) * ldc + mA + 8] = v3;
            }
        }
    } else {
        #pragma unroll
        for (int tm = 0; tm < 4; tm++) {
            const int mA = m0 + wm + tm * 16 + g;
            #pragma unroll
            for (int tn = 0; tn < 4; tn++) {
                const int n = n0 + wn + tn * 8 + t4 * 2;
                float v0 = alpha * acc[tm][tn][0], v1 = alpha * acc[tm][tn][1];
                float v2 = alpha * acc[tm][tn][2], v3 = alpha * acc[tm][tn][3];
                if (rnd) { v0 = rtf(v0); v1 = rtf(v1); v2 = rtf(v2); v3 = rtf(v3); }
                *(float2*)(C + (long)mA * ldc + n)       = make_float2(v0, v1);
                *(float2*)(C + (long)(mA + 8) * ldc + n) = make_float2(v2, v3);
            }
        }
    }
}

// ---------------------------------------------------------------------------
// Causal row softmax, in place. Writes tf32-rounded P (PV GEMM input) and
// zero-fills (q, 128-tile boundary) so PV's causal K bound reads only zeros.
// ---------------------------------------------------------------------------
__global__ void __launch_bounds__(256)
softmax_causal(float* __restrict__ S_, int S)
{
    const long row = blockIdx.x;            // b*S + q
    const int  q   = (int)(row & (long)(S - 1));
    float* p = S_ + row * (long)S;
    const int n = q + 1;

    __shared__ float buf[SEQ];
    __shared__ float red[256];
    const int tid = threadIdx.x;

    float lmax = -3.4e38f;
    for (int i = tid; i < n; i += 256) {
        float v = p[i];
        buf[i] = v;
        lmax = fmaxf(lmax, v);
    }
    red[tid] = lmax;
    __syncthreads();
    #pragma unroll
    for (int s = 128; s > 0; s >>= 1) {
        if (tid < s) red[tid] = fmaxf(red[tid], red[tid + s]);
        __syncthreads();
    }
    const float m = red[0];
    __syncthreads();

    float lsum = 0.f;
    for (int i = tid; i < n; i += 256) {
        float e = __expf(buf[i] - m);
        buf[i] = e;
        lsum += e;
    }
    red[tid] = lsum;
    __syncthreads();
    #pragma unroll
    for (int s = 128; s > 0; s >>= 1) {
        if (tid < s) red[tid] += red[tid + s];
        __syncthreads();
    }
    const float inv = 1.0f / red[0];
    __syncthreads();

    for (int i = tid; i < n; i += 256) p[i] = rtf(buf[i] * inv);
    const int zend = ((q >> 7) + 1) << 7;   // next multiple of BM=128
    for (int i = n + tid; i < zend; i += 256) p[i] = 0.f;
}

// ---------------------------------------------------------------------------
extern "C" void kernel_launch(void* const* d_in, const int* in_sizes, int n_in,
                              void* d_out, int out_size)
{
    const float* x  = (const float*)d_in[0];
    const float* Wq = (const float*)d_in[1];
    const float* Wk = (const float*)d_in[2];
    const float* Wv = (const float*)d_in[3];
    float* out = (float*)d_out;

    float *Q, *Kd, *Vt, *Sc, *Xr, *Wqr, *Wkr, *Wvr;
    cudaGetSymbolAddress((void**)&Q,   g_Q);
    cudaGetSymbolAddress((void**)&Kd,  g_K);
    cudaGetSymbolAddress((void**)&Vt,  g_V);
    cudaGetSymbolAddress((void**)&Sc,  g_S);
    cudaGetSymbolAddress((void**)&Xr,  g_X);
    cudaGetSymbolAddress((void**)&Wqr, g_Wq);
    cudaGetSymbolAddress((void**)&Wkr, g_Wk);
    cudaGetSymbolAddress((void**)&Wvr, g_Wv);

    cudaFuncSetAttribute(gemm_mma, cudaFuncAttributeMaxDynamicSharedMemorySize,
                         SMEM_DYN);

    // tf32-round all GEMM inputs once
    const int nx4 = (MTOT * DIM) / 4, nw4 = (DIM * DIM) / 4;
    round_tf32<<<(nx4 + 255) / 256, 256>>>((const float4*)x,  (float4*)Xr,  nx4);
    round_tf32<<<(nw4 + 255) / 256, 256>>>((const float4*)Wq, (float4*)Wqr, nw4);
    round_tf32<<<(nw4 + 255) / 256, 256>>>((const float4*)Wk, (float4*)Wkr, nw4);
    round_tf32<<<(nw4 + 255) / 256, 256>>>((const float4*)Wv, (float4*)Wvr, nw4);

    // QKV projections (outputs tf32-rounded); V written transposed (Vt)
    dim3 gP(DIM / BN, MTOT / BM, 1);
    gemm_mma<<<gP, NTHR, SMEM_DYN>>>(Xr, Wqr, Q,  DIM, DIM, DIM, DIM,
                                     0, 0, 0, 1.0f, 8);
    gemm_mma<<<gP, NTHR, SMEM_DYN>>>(Xr, Wkr, Kd, DIM, DIM, DIM, DIM,
                                     0, 0, 0, 1.0f, 8);
    gemm_mma<<<gP, NTHR, SMEM_DYN>>>(Xr, Wvr, Vt, DIM, DIM, DIM, MTOT,
                                     0, 0, 0, 1.0f, 2 | 8);   // transC + round

    // scores = (1/32) * Q K^T per batch, causal tile skip (no rounding)
    const long sQK = (long)SEQ * DIM;
    const long sSS = (long)SEQ * SEQ;
    dim3 gS(SEQ / BN, SEQ / BM, BATCH);
    gemm_mma<<<gS, NTHR, SMEM_DYN>>>(Q, Kd, Sc, DIM, DIM, DIM, SEQ,
                                     sQK, sQK, sSS, 0.03125f, 1);

    softmax_causal<<<BATCH * SEQ, 256>>>(Sc, SEQ);

    // out = P V per batch : NT with B = Vt (ldb = MTOT), causal K bound
    dim3 gPV(DIM / BN, SEQ / BM, BATCH);
    gemm_mma<<<gPV, NTHR, SMEM_DYN>>>(Sc, Vt, out, SEQ, SEQ, MTOT, DIM,
                                      sSS, (long)SEQ, sQK, 1.0f, 4);
}

// round 9
// speedup vs baseline: 4.4470x; 1.0860x over previous
#include <cuda_runtime.h>
#include <cstdint>

#define BATCH 4
#define SEQ   4096
#define DIM   1024
#define MTOT  (BATCH * SEQ)      // 16384

#define BM 128
#define BN 128
#define BK 32
#define NTHR 256
#define PADS 40                   // smem row stride in floats (conflict-free LDS.64)
#define BUF_FLOATS (BM * PADS)    // 5120 floats = 20480 B per tile buffer
#define BUF_BYTES  (BUF_FLOATS * 4)
#define SMEM_DYN (2 * 2 * BUF_BYTES)   // A0,B0,A1,B1 = 81920 B (2 CTA/SM fits)

// Scratch (allocation-free rule: __device__ globals)
__device__ float g_Q[(size_t)MTOT * DIM];
__device__ float g_K[(size_t)MTOT * DIM];
__device__ float g_V[(size_t)MTOT * DIM];          // holds V^T: [DIM][MTOT]
__device__ float g_S[(size_t)BATCH * SEQ * SEQ];
__device__ float g_X[(size_t)MTOT * DIM];          // tf32-rounded x
__device__ float g_Wq[(size_t)DIM * DIM];
__device__ float g_Wk[(size_t)DIM * DIM];
__device__ float g_Wv[(size_t)DIM * DIM];

// ---------------------------------------------------------------------------
static __device__ __forceinline__ uint32_t s2u(const void* p) {
    uint32_t a;
    asm("{ .reg .u64 t; cvta.to.shared.u64 t, %1; cvt.u32.u64 %0, t; }"
        : "=r"(a) : "l"(p));
    return a;
}
static __device__ __forceinline__ uint32_t f2tf32(float f) {
    uint32_t r;
    asm("cvt.rna.tf32.f32 %0, %1;" : "=r"(r) : "f"(f));
    return r;
}
static __device__ __forceinline__ float rtf(float f) {
    return __uint_as_float(f2tf32(f));
}
static __device__ __forceinline__ void cpasync16(uint32_t saddr, const void* gaddr) {
    asm volatile("cp.async.cg.shared.global [%0], [%1], 16;"
                 :: "r"(saddr), "l"(gaddr) : "memory");
}
static __device__ __forceinline__ void cpcommit() {
    asm volatile("cp.async.commit_group;" ::: "memory");
}
static __device__ __forceinline__ void cpwait0() {
    asm volatile("cp.async.wait_group 0;" ::: "memory");
}
static __device__ __forceinline__ void mma_tf32(float* c, uint32_t a0, uint32_t a1,
                                                uint32_t a2, uint32_t a3,
                                                uint32_t b0, uint32_t b1) {
    asm volatile(
        "mma.sync.aligned.m16n8k8.row.col.f32.tf32.tf32.f32 "
        "{%0,%1,%2,%3}, {%4,%5,%6,%7}, {%8,%9}, {%0,%1,%2,%3};"
        : "+f"(c[0]), "+f"(c[1]), "+f"(c[2]), "+f"(c[3])
        : "r"(a0), "r"(a1), "r"(a2), "r"(a3), "r"(b0), "r"(b1));
}

// ---------------------------------------------------------------------------
// Pre-round a tensor to tf32 (rna), float4 granularity.
// ---------------------------------------------------------------------------
__global__ void __launch_bounds__(256)
round_tf32(const float4* __restrict__ in, float4* __restrict__ out, int n4)
{
    int i = blockIdx.x * 256 + threadIdx.x;
    if (i < n4) {
        float4 v = in[i];
        out[i] = make_float4(rtf(v.x), rtf(v.y), rtf(v.z), rtf(v.w));
    }
}

// ---------------------------------------------------------------------------
// tf32 mma.sync NT GEMM: C[m][n] = alpha * sum_k A[m][k] * B[n][k]
// Inputs must already be tf32-rounded. 2-stage cp.async pipeline, one
// __syncthreads per K-chunk. Fragment loads are LDS.64 with the k-pair
// permutation {t4, t4+4} -> {2t4, 2t4+1} applied identically to A and B
// (exact: the MMA's k order within a k8 block is a shared bijection).
// flags: 1 = causal tile skip (n0 > m0), 2 = transposed epilogue (C[n][m]),
//        4 = causal K bound (kend = m0 + BM), 8 = round output to tf32
// ---------------------------------------------------------------------------
__global__ void __launch_bounds__(NTHR, 2)
gemm_mma(const float* __restrict__ A, const float* __restrict__ B,
         float* __restrict__ C, int K, int lda, int ldb, int ldc,
         long sA, long sB, long sC, float alpha, int flags)
{
    const int m0 = blockIdx.y * BM;
    const int n0 = blockIdx.x * BN;
    if ((flags & 1) && n0 > m0) return;

    A += (long)blockIdx.z * sA;
    B += (long)blockIdx.z * sB;
    C += (long)blockIdx.z * sC;

    extern __shared__ float smf[];
    const uint32_t sa = s2u(smf);

    const int tid  = threadIdx.x;
    const int lane = tid & 31;
    const int w    = tid >> 5;
    const int wm   = (w >> 2) * 64;     // warp tile M origin (0 or 64)
    const int wn   = (w & 3) * 32;      // warp tile N origin (0..96)
    const int g    = lane >> 2;         // 0..7
    const int t4   = lane & 3;          // 0..3

    const int kend = (flags & 4) ? min(K, m0 + BM) : K;
    const int nc   = kend / BK;

    // Global->smem geometry: 4 x 16B cp.async per thread per operand per chunk
    const int lr  = tid >> 3;           // 0..31 base row
    const int lc4 = (tid & 7) * 4;      // float col 0,4,...,28
    const float* Ag[4]; const float* Bg[4];
    uint32_t sob[4];                    // smem byte offset within a buffer
    #pragma unroll
    for (int i = 0; i < 4; i++) {
        const int row = lr + 32 * i;
        Ag[i] = A + (long)(m0 + row) * lda + lc4;
        Bg[i] = B + (long)(n0 + row) * ldb + lc4;
        sob[i] = (uint32_t)(row * PADS + lc4) * 4u;
    }

    float acc[4][4][4];
    #pragma unroll
    for (int i = 0; i < 4; i++)
        #pragma unroll
        for (int j = 0; j < 4; j++)
            #pragma unroll
            for (int k = 0; k < 4; k++) acc[i][j][k] = 0.f;

    // prologue: issue chunk 0 into stage 0
    {
        #pragma unroll
        for (int i = 0; i < 4; i++) {
            cpasync16(sa + sob[i], Ag[i]);
            cpasync16(sa + BUF_BYTES + sob[i], Bg[i]);
            Ag[i] += BK; Bg[i] += BK;
        }
        cpcommit();
    }

    for (int c = 0; c < nc; c++) {
        cpwait0();            // chunk c's copies complete (only group in flight)
        __syncthreads();      // data visible; other stage fully consumed

        if (c + 1 < nc) {     // issue chunk c+1 into the other stage
            const uint32_t st = (uint32_t)((c + 1) & 1) * 2u * BUF_BYTES;
            #pragma unroll
            for (int i = 0; i < 4; i++) {
                cpasync16(sa + st + sob[i], Ag[i]);
                cpasync16(sa + st + BUF_BYTES + sob[i], Bg[i]);
                Ag[i] += BK; Bg[i] += BK;
            }
            cpcommit();
        }

        const uint32_t* Au = (const uint32_t*)(smf + (c & 1) * 2 * BUF_FLOATS);
        const uint32_t* Bu = Au + BUF_FLOATS;
        #pragma unroll
        for (int ks = 0; ks < 4; ks++) {
            const int kp = ks * 8 + 2 * t4;     // permuted k pair base
            uint32_t af[4][4];
            #pragma unroll
            for (int tm = 0; tm < 4; tm++) {
                const int m = wm + tm * 16 + g;
                uint2 lo = *(const uint2*)(Au + m * PADS + kp);
                uint2 hi = *(const uint2*)(Au + (m + 8) * PADS + kp);
                af[tm][0] = lo.x; af[tm][2] = lo.y;   // k=2t4, 2t4+1
                af[tm][1] = hi.x; af[tm][3] = hi.y;
            }
            uint32_t bf[4][2];
            #pragma unroll
            for (int tn = 0; tn < 4; tn++) {
                const int n = wn + tn * 8 + g;
                uint2 bv = *(const uint2*)(Bu + n * PADS + kp);
                bf[tn][0] = bv.x; bf[tn][1] = bv.y;
            }
            #pragma unroll
            for (int tm = 0; tm < 4; tm++)
                #pragma unroll
                for (int tn = 0; tn < 4; tn++)
                    mma_tf32(acc[tm][tn], af[tm][0], af[tm][1], af[tm][2],
                             af[tm][3], bf[tn][0], bf[tn][1]);
        }
        // next iteration's __syncthreads closes this stage before refill
    }

    // Epilogue. Thread owns (row = wm+tm*16+g[+8], cols = wn+tn*8+t4*2, +1)
    const bool rnd = (flags & 8) != 0;
    if (flags & 2) {
        #pragma unroll
        for (int tm = 0; tm < 4; tm++) {
            const int mA = m0 + wm + tm * 16 + g;
            #pragma unroll
            for (int tn = 0; tn < 4; tn++) {
                const int n = n0 + wn + tn * 8 + t4 * 2;
                float v0 = alpha * acc[tm][tn][0], v1 = alpha * acc[tm][tn][1];
                float v2 = alpha * acc[tm][tn][2], v3 = alpha * acc[tm][tn][3];
                if (rnd) { v0 = rtf(v0); v1 = rtf(v1); v2 = rtf(v2); v3 = rtf(v3); }
                C[(long)n * ldc + mA]           = v0;
                C[(long)(n + 1) * ldc + mA]     = v1;
                C[(long)n * ldc + mA + 8]       = v2;
                C[(long)(n + 1) * ldc + mA + 8] = v3;
            }
        }
    } else {
        #pragma unroll
        for (int tm = 0; tm < 4; tm++) {
            const int mA = m0 + wm + tm * 16 + g;
            #pragma unroll
            for (int tn = 0; tn < 4; tn++) {
                const int n = n0 + wn + tn * 8 + t4 * 2;
                float v0 = alpha * acc[tm][tn][0], v1 = alpha * acc[tm][tn][1];
                float v2 = alpha * acc[tm][tn][2], v3 = alpha * acc[tm][tn][3];
                if (rnd) { v0 = rtf(v0); v1 = rtf(v1); v2 = rtf(v2); v3 = rtf(v3); }
                *(float2*)(C + (long)mA * ldc + n)       = make_float2(v0, v1);
                *(float2*)(C + (long)(mA + 8) * ldc + n) = make_float2(v2, v3);
            }
        }
    }
}

// ---------------------------------------------------------------------------
// Causal row softmax, in place. Writes tf32-rounded P (PV GEMM input) and
// zero-fills (q, 128-tile boundary) so PV's causal K bound reads only zeros.
// ---------------------------------------------------------------------------
__global__ void __launch_bounds__(256)
softmax_causal(float* __restrict__ S_, int S)
{
    const long row = blockIdx.x;            // b*S + q
    const int  q   = (int)(row & (long)(S - 1));
    float* p = S_ + row * (long)S;
    const int n = q + 1;

    __shared__ float buf[SEQ];
    __shared__ float red[256];
    const int tid = threadIdx.x;

    float lmax = -3.4e38f;
    for (int i = tid; i < n; i += 256) {
        float v = p[i];
        buf[i] = v;
        lmax = fmaxf(lmax, v);
    }
    red[tid] = lmax;
    __syncthreads();
    #pragma unroll
    for (int s = 128; s > 0; s >>= 1) {
        if (tid < s) red[tid] = fmaxf(red[tid], red[tid + s]);
        __syncthreads();
    }
    const float m = red[0];
    __syncthreads();

    float lsum = 0.f;
    for (int i = tid; i < n; i += 256) {
        float e = __expf(buf[i] - m);
        buf[i] = e;
        lsum += e;
    }
    red[tid] = lsum;
    __syncthreads();
    #pragma unroll
    for (int s = 128; s > 0; s >>= 1) {
        if (tid < s) red[tid] += red[tid + s];
        __syncthreads();
    }
    const float inv = 1.0f / red[0];
    __syncthreads();

    for (int i = tid; i < n; i += 256) p[i] = rtf(buf[i] * inv);
    const int zend = ((q >> 7) + 1) << 7;   // next multiple of BM=128
    for (int i = n + tid; i < zend; i += 256) p[i] = 0.f;
}

// ---------------------------------------------------------------------------
extern "C" void kernel_launch(void* const* d_in, const int* in_sizes, int n_in,
                              void* d_out, int out_size)
{
    const float* x  = (const float*)d_in[0];
    const float* Wq = (const float*)d_in[1];
    const float* Wk = (const float*)d_in[2];
    const float* Wv = (const float*)d_in[3];
    float* out = (float*)d_out;

    float *Q, *Kd, *Vt, *Sc, *Xr, *Wqr, *Wkr, *Wvr;
    cudaGetSymbolAddress((void**)&Q,   g_Q);
    cudaGetSymbolAddress((void**)&Kd,  g_K);
    cudaGetSymbolAddress((void**)&Vt,  g_V);
    cudaGetSymbolAddress((void**)&Sc,  g_S);
    cudaGetSymbolAddress((void**)&Xr,  g_X);
    cudaGetSymbolAddress((void**)&Wqr, g_Wq);
    cudaGetSymbolAddress((void**)&Wkr, g_Wk);
    cudaGetSymbolAddress((void**)&Wvr, g_Wv);

    cudaFuncSetAttribute(gemm_mma, cudaFuncAttributeMaxDynamicSharedMemorySize,
                         SMEM_DYN);

    // tf32-round all GEMM inputs once
    const int nx4 = (MTOT * DIM) / 4, nw4 = (DIM * DIM) / 4;
    round_tf32<<<(nx4 + 255) / 256, 256>>>((const float4*)x,  (float4*)Xr,  nx4);
    round_tf32<<<(nw4 + 255) / 256, 256>>>((const float4*)Wq, (float4*)Wqr, nw4);
    round_tf32<<<(nw4 + 255) / 256, 256>>>((const float4*)Wk, (float4*)Wkr, nw4);
    round_tf32<<<(nw4 + 255) / 256, 256>>>((const float4*)Wv, (float4*)Wvr, nw4);

    // QKV projections (outputs tf32-rounded); V written transposed (Vt)
    dim3 gP(DIM / BN, MTOT / BM, 1);
    gemm_mma<<<gP, NTHR, SMEM_DYN>>>(Xr, Wqr, Q,  DIM, DIM, DIM, DIM,
                                     0, 0, 0, 1.0f, 8);
    gemm_mma<<<gP, NTHR, SMEM_DYN>>>(Xr, Wkr, Kd, DIM, DIM, DIM, DIM,
                                     0, 0, 0, 1.0f, 8);
    gemm_mma<<<gP, NTHR, SMEM_DYN>>>(Xr, Wvr, Vt, DIM, DIM, DIM, MTOT,
                                     0, 0, 0, 1.0f, 2 | 8);   // transC + round

    // scores = (1/32) * Q K^T per batch, causal tile skip (no rounding)
    const long sQK = (long)SEQ * DIM;
    const long sSS = (long)SEQ * SEQ;
    dim3 gS(SEQ / BN, SEQ / BM, BATCH);
    gemm_mma<<<gS, NTHR, SMEM_DYN>>>(Q, Kd, Sc, DIM, DIM, DIM, SEQ,
                                     sQK, sQK, sSS, 0.03125f, 1);

    softmax_causal<<<BATCH * SEQ, 256>>>(Sc, SEQ);

    // out = P V per batch : NT with B = Vt (ldb = MTOT), causal K bound
    dim3 gPV(DIM / BN, SEQ / BM, BATCH);
    gemm_mma<<<gPV, NTHR, SMEM_DYN>>>(Sc, Vt, out, SEQ, SEQ, MTOT, DIM,
                                      sSS, (long)SEQ, sQK, 1.0f, 4);
}